// round 14
// baseline (speedup 1.0000x reference)
#include <cuda_runtime.h>
#include <cuda_fp16.h>
#include <math.h>
#include <stdint.h>

// ---------------------------------------------------------------------------
// Problem constants
// ---------------------------------------------------------------------------
constexpr int NB   = 16;
constexpr int CH   = 512;
constexpr int NPIX = 1024;
constexpr int NGRP = 32;

// GEMM tiling: CTA 128x128, BK=32, 8 warps (2M x 4N), warp tile 64x32
constexpr int TM = 128, TN = 128, TK = 32;

constexpr int A_STAGE     = 8192;                   // A: 128 rows * 64B
constexpr int B_STAGE     = 8192;                   // B: 128 rows * 64B
constexpr int STAGE_BYTES = A_STAGE + B_STAGE;      // 16384
constexpr int NSTAGE      = 4;                      // 65536 B of stages
constexpr int SPITCH      = 129;                    // fp32 epilogue pitch
constexpr int SMEM_BYTES  = TM * SPITCH * 4;        // 66048 (> 4*16384)

// ---------------------------------------------------------------------------
// Scratch (__device__ globals). All GEMM operands single fp16.
// ---------------------------------------------------------------------------
#define BALIGN __align__(256)
__device__ BALIGN __half g_ht[(size_t)NB * NPIX * CH];    // B of QKV   [b][p][c]
__device__ BALIGN __half g_q [(size_t)NB * NPIX * CH];    // A of scores[b][p][c]
__device__ BALIGN __half g_k [(size_t)NB * NPIX * CH];    // B of scores[b][p][c]
__device__ BALIGN __half g_v [(size_t)NB * CH * NPIX];    // B of PV    [b][c][p]
__device__ BALIGN __half g_p [(size_t)NB * NPIX * NPIX];  // A of PV    [b][i][j]
__device__ BALIGN __half g_ot[(size_t)NB * NPIX * CH];    // B of proj  [b][p][c]
__device__ BALIGN __half g_wq[(size_t)3 * CH * CH];       // A of QKV
__device__ BALIGN __half g_wp[(size_t)CH * CH];           // A of proj
__device__ BALIGN float  g_attn[(size_t)NB * NPIX * NPIX];
__device__ float g_stats[NB * NGRP * 2];

// ---------------------------------------------------------------------------
// helpers
// ---------------------------------------------------------------------------
__device__ __forceinline__ uint32_t smem_u32(const void* p) {
    uint32_t a;
    asm("{ .reg .u64 t; cvta.to.shared.u64 t, %1; cvt.u32.u64 %0, t; }" : "=r"(a) : "l"(p));
    return a;
}

#define CP16(sm, gp) asm volatile("cp.async.cg.shared.global [%0], [%1], 16;" :: "r"(sm), "l"(gp))
#define CP_COMMIT()  asm volatile("cp.async.commit_group;" ::: "memory")
#define CP_WAIT0()   asm volatile("cp.async.wait_group 0;" ::: "memory")
#define CP_WAIT2()   asm volatile("cp.async.wait_group 2;" ::: "memory")

#define LDSM4(r0, r1, r2, r3, a) \
    asm volatile("ldmatrix.sync.aligned.m8n8.x4.shared.b16 {%0,%1,%2,%3}, [%4];" \
                 : "=r"(r0), "=r"(r1), "=r"(r2), "=r"(r3) : "r"(a))

#define MMA_F16(d, a, b0, b1) \
    asm volatile("mma.sync.aligned.m16n8k16.row.col.f32.f16.f16.f32 " \
                 "{%0,%1,%2,%3},{%4,%5,%6,%7},{%8,%9},{%0,%1,%2,%3};" \
                 : "+f"((d)[0]), "+f"((d)[1]), "+f"((d)[2]), "+f"((d)[3]) \
                 : "r"((a)[0]), "r"((a)[1]), "r"((a)[2]), "r"((a)[3]), "r"(b0), "r"(b1))

// ---------------------------------------------------------------------------
// GroupNorm phase 1: per-(b,g) mean / rstd
// ---------------------------------------------------------------------------
__global__ __launch_bounds__(256) void gn_stats_kernel(
    const float* __restrict__ x, float* __restrict__ stats)
{
    const int GSZ = (CH / NGRP) * NPIX;
    const int bg  = blockIdx.x;
    const float4* xv = (const float4*)(x + (size_t)bg * GSZ);
    const int tid = threadIdx.x;

    float s = 0.f, ss = 0.f;
    for (int i = tid; i < GSZ / 4; i += 256) {
        float4 v = xv[i];
        s  += v.x + v.y + v.z + v.w;
        ss += v.x * v.x + v.y * v.y + v.z * v.z + v.w * v.w;
    }
    __shared__ float rs[256], rss[256];
    rs[tid] = s; rss[tid] = ss;
    __syncthreads();
    for (int o = 128; o > 0; o >>= 1) {
        if (tid < o) { rs[tid] += rs[tid + o]; rss[tid] += rss[tid + o]; }
        __syncthreads();
    }
    if (tid == 0) {
        float mu  = rs[0] / GSZ;
        float var = rss[0] / GSZ - mu * mu;
        stats[bg * 2]     = mu;
        stats[bg * 2 + 1] = rsqrtf(var + 1e-5f);
    }
}

// ---------------------------------------------------------------------------
// GroupNorm phase 2: normalize + transpose -> ht[b][p][c] (fp16)
// ---------------------------------------------------------------------------
__global__ __launch_bounds__(256) void gn_apply_kernel(
    const float* __restrict__ x, const float* __restrict__ gamma,
    const float* __restrict__ beta, const float* __restrict__ stats,
    __half* __restrict__ ht)
{
    __shared__ float s[32][33];
    const int p0 = blockIdx.x * 32, c0 = blockIdx.y * 32, b = blockIdx.z;
    const int tid = threadIdx.x;

    #pragma unroll
    for (int q = 0; q < 4; q++) {
        int ci = (tid >> 5) + q * 8, pj = tid & 31;
        int c = c0 + ci;
        float xv = x[((size_t)b * CH + c) * NPIX + p0 + pj];
        int g = c >> 4;
        float mu = stats[(b * NGRP + g) * 2], rinv = stats[(b * NGRP + g) * 2 + 1];
        s[ci][pj] = (xv - mu) * rinv * gamma[c] + beta[c];
    }
    __syncthreads();
    #pragma unroll
    for (int q = 0; q < 4; q++) {
        int cj = tid & 31, pi = (tid >> 5) + q * 8;
        size_t o = (size_t)b * NPIX * CH + (size_t)(p0 + pi) * CH + c0 + cj;
        ht[o] = __float2half(s[cj][pi]);
    }
}

// ---------------------------------------------------------------------------
// Warp-per-row softmax -> fp16 P. 8 warps per block = 8 rows; no barriers,
// no smem; each lane holds 32 values (8 x float4, MLP=8).
// ---------------------------------------------------------------------------
__global__ __launch_bounds__(256) void softmax_kernel(
    const float* __restrict__ attn, __half* __restrict__ ph)
{
    const int lane = threadIdx.x & 31;
    const size_t row = (size_t)blockIdx.x * 8 + (threadIdx.x >> 5);
    const float4* p = (const float4*)(attn + row * NPIX) + lane;

    float4 v[8];
    #pragma unroll
    for (int j = 0; j < 8; j++) v[j] = p[j * 32];

    float m = -1e30f;
    #pragma unroll
    for (int j = 0; j < 8; j++)
        m = fmaxf(m, fmaxf(fmaxf(v[j].x, v[j].y), fmaxf(v[j].z, v[j].w)));
    #pragma unroll
    for (int o = 16; o > 0; o >>= 1) m = fmaxf(m, __shfl_xor_sync(~0u, m, o));

    float s = 0.f;
    #pragma unroll
    for (int j = 0; j < 8; j++) {
        v[j].x = __expf(v[j].x - m); v[j].y = __expf(v[j].y - m);
        v[j].z = __expf(v[j].z - m); v[j].w = __expf(v[j].w - m);
        s += v[j].x + v[j].y + v[j].z + v[j].w;
    }
    #pragma unroll
    for (int o = 16; o > 0; o >>= 1) s += __shfl_xor_sync(~0u, s, o);

    const float rinv = 1.f / s;
    uint2* po = (uint2*)(ph + row * NPIX) + lane;   // 4 halves per store
    #pragma unroll
    for (int j = 0; j < 8; j++) {
        __half2 h0(__float2half(v[j].x * rinv), __float2half(v[j].y * rinv));
        __half2 h1(__float2half(v[j].z * rinv), __float2half(v[j].w * rinv));
        uint2 u;
        u.x = *(uint32_t*)&h0;
        u.y = *(uint32_t*)&h1;
        po[j * 32] = u;
    }
}

// ---------------------------------------------------------------------------
// fp32 -> fp16, both weight tensors in one grid-stride launch
// ---------------------------------------------------------------------------
__global__ __launch_bounds__(256) void pack_kernel(
    const float* __restrict__ w0, __half* __restrict__ o0, int n0,
    const float* __restrict__ w1, __half* __restrict__ o1, int n1)
{
    const int stride = gridDim.x * 256;
    for (int i = (blockIdx.x * 256 + threadIdx.x) * 2; i < n0; i += stride * 2)
        *(__half2*)(o0 + i) = __half2(__float2half(w0[i]), __float2half(w0[i + 1]));
    for (int i = (blockIdx.x * 256 + threadIdx.x) * 2; i < n1; i += stride * 2)
        *(__half2*)(o1 + i) = __half2(__float2half(w1[i]), __float2half(w1[i + 1]));
}

// ---------------------------------------------------------------------------
// fp16 HMMA GEMM: D[m][n] = sum_k A[m][k]*B[n][k] (both k-major, fp16).
// CTA 128x128, BK=32, 8 warps (2M x 4N), warp tile 64x32, 4-stage cp.async,
// one __syncthreads per k-iter, 2 CTAs/SM.
// smem rows 64B, 16B units XOR-swizzled by (row>>1)&3.
// Direct-register epilogue for row-major outputs (scores/PV/proj/V);
// smem-staged transpose only for Q/K.
// EPI 0: QKV  1: scores  2: PV  3: proj(+bias+residual)
// ---------------------------------------------------------------------------
template<int EPI>
__global__ __launch_bounds__(256, 2) void tc_gemm(
    const __half* __restrict__ Ag, const __half* __restrict__ Bg,
    long long sAb, long long sBb, int ldA, int ldB, int K,
    const float* __restrict__ bias, float scale,
    float* __restrict__ outf,
    __half* __restrict__ o0, __half* __restrict__ o1, __half* __restrict__ o2,
    const float* __restrict__ resid)
{
    extern __shared__ char smem[];
    const uint32_t sb = smem_u32(smem);
    const int tid = threadIdx.x;
    const int lane = tid & 31, wid = tid >> 5;
    const int bz = blockIdx.z;
    const int m0 = blockIdx.y * TM;
    const int n0 = blockIdx.x * TN;

    const __half* Ap = Ag + (size_t)bz * sAb + (size_t)m0 * ldA;
    const __half* Bp = Bg + (size_t)bz * sBb + (size_t)n0 * ldB;

    // loaders: row = tid>>1 (0..127), 2 of 4 16B units each
    const int lrow = tid >> 1;
    const int usel = tid & 1;

    auto load_tile = [&](int buf, int k0) {
        const uint32_t sa  = sb + buf * STAGE_BYTES;
        const uint32_t sbB = sa + A_STAGE;
        const int rsw = (lrow >> 1) & 3;
        #pragma unroll
        for (int j = 0; j < 2; j++) {
            const int u = usel * 2 + j;
            const uint32_t sw = (uint32_t)((u ^ rsw) << 4);
            CP16(sa  + lrow * 64 + sw, Ap + (size_t)lrow * ldA + k0 + u * 8);
            CP16(sbB + lrow * 64 + sw, Bp + (size_t)lrow * ldB + k0 + u * 8);
        }
    };

    // warp layout: 2 (M) x 4 (N), warp tile 64x32
    const int wm = wid >> 2, wn = wid & 3;
    const int m_base = wm * 64, n_base = wn * 32;

    // ldmatrix lane mapping
    const int amat = lane >> 3;
    const int arow = (amat & 1) * 8 + (lane & 7);
    const int auadd = amat >> 1;
    const int bmat = lane >> 3;
    const int bnrow = (bmat >> 1) * 8 + (lane & 7);
    const int buadd = bmat & 1;

    float acc[4][4][4] = {};

    const int nk = K / TK;
    load_tile(0, 0);
    CP_COMMIT();
    load_tile(1, TK);
    CP_COMMIT();
    load_tile(2, 2 * TK);
    CP_COMMIT();

    for (int i = 0; i < nk; i++) {
        if (i == nk - 1) { CP_WAIT0(); } else { CP_WAIT2(); }
        __syncthreads();
        if (i + 3 < nk) {
            load_tile((i + 3) % NSTAGE, (i + 3) * TK);
            CP_COMMIT();
        }
        const uint32_t sa  = sb + (i % NSTAGE) * STAGE_BYTES;
        const uint32_t sbB = sa + A_STAGE;

        #pragma unroll
        for (int kk = 0; kk < 2; kk++) {
            uint32_t bh[8];
            #pragma unroll
            for (int np = 0; np < 2; np++) {
                const int n = n_base + np * 16 + bnrow;
                const int uh = kk * 2 + buadd;
                LDSM4(bh[np * 4 + 0], bh[np * 4 + 1], bh[np * 4 + 2], bh[np * 4 + 3],
                      sbB + n * 64 + ((uh ^ ((n >> 1) & 3)) << 4));
            }
            uint32_t ah[4][4];
            #pragma unroll
            for (int mt = 0; mt < 4; mt++) {
                const int row = m_base + mt * 16 + arow;
                const int uh = kk * 2 + auadd;
                LDSM4(ah[mt][0], ah[mt][1], ah[mt][2], ah[mt][3],
                      sa + row * 64 + ((uh ^ ((row >> 1) & 3)) << 4));
            }
            #pragma unroll
            for (int mt = 0; mt < 4; mt++)
                #pragma unroll
                for (int nt = 0; nt < 4; nt++) {
                    const int r = (nt >> 1) * 4 + (nt & 1) * 2;
                    MMA_F16(acc[mt][nt], ah[mt], bh[r], bh[r + 1]);
                }
        }
    }

    // ---- epilogues ----
    const int rowL = lane >> 2;            // 0..7
    const int colL = (lane & 3) * 2;       // 0..6

    if (EPI == 0 && m0 < 2 * CH) {
        // Q or K tile: needs transpose -> smem staging
        __syncthreads();
        float* s = (float*)smem;
        #pragma unroll
        for (int mt = 0; mt < 4; mt++)
            #pragma unroll
            for (int nt = 0; nt < 4; nt++)
                #pragma unroll
                for (int r = 0; r < 4; r++) {
                    const int row = m_base + mt * 16 + rowL + (r >= 2 ? 8 : 0);
                    const int col = n_base + nt * 8 + colL + (r & 1);
                    s[row * SPITCH + col] = acc[mt][nt][r];
                }
        __syncthreads();
        __half* d = (m0 < CH ? o0 : o1) + (size_t)bz * NPIX * CH;
        const int coff = m0 & (CH - 1);
        for (int it = 0; it < 32; it++) {
            const int idx = it * 512 + tid * 2;
            const int n = idx >> 7, m = idx & 127;
            float v0 = s[m * SPITCH + n] + bias[m0 + m];
            float v1 = s[(m + 1) * SPITCH + n] + bias[m0 + m + 1];
            const size_t o = (size_t)(n0 + n) * CH + coff + m;
            *(__half2*)(d + o) = __half2(__float2half(v0), __float2half(v1));
        }
    } else {
        // direct-register writers: acc pairs are adjacent output columns
        #pragma unroll
        for (int mt = 0; mt < 4; mt++) {
            #pragma unroll
            for (int nt = 0; nt < 4; nt++) {
                const int col = n_base + nt * 8 + colL;
                #pragma unroll
                for (int h = 0; h < 2; h++) {       // h=0: rows+0, h=1: rows+8
                    const int row = m_base + mt * 16 + rowL + h * 8;
                    const float a0 = acc[mt][nt][h * 2];
                    const float a1 = acc[mt][nt][h * 2 + 1];
                    if (EPI == 0) {          // V tile -> v[b][c][p] fp16 (+bias)
                        const int c = m0 - 2 * CH + row;
                        const float bv = bias[m0 + row];
                        const size_t o = ((size_t)bz * CH + c) * NPIX + n0 + col;
                        *(__half2*)(o2 + o) =
                            __half2(__float2half(a0 + bv), __float2half(a1 + bv));
                    } else if (EPI == 1) {   // scores fp32 * scale
                        const size_t o = ((size_t)bz * NPIX + m0 + row) * NPIX + n0 + col;
                        *(float2*)(outf + o) = make_float2(a0 * scale, a1 * scale);
                    } else if (EPI == 2) {   // Ot fp16 [p][c]
                        const size_t o = ((size_t)bz * NPIX + m0 + row) * CH + n0 + col;
                        *(__half2*)(o0 + o) =
                            __half2(__float2half(a0), __float2half(a1));
                    } else {                 // proj + bias + residual fp32
                        const float bv = bias[m0 + row];
                        const size_t o = ((size_t)bz * CH + m0 + row) * NPIX + n0 + col;
                        float2 rv = *(const float2*)(resid + o);
                        *(float2*)(outf + o) =
                            make_float2(a0 + bv + rv.x, a1 + bv + rv.y);
                    }
                }
            }
        }
    }
}

// ---------------------------------------------------------------------------
extern "C" void kernel_launch(void* const* d_in, const int* in_sizes, int n_in,
                              void* d_out, int out_size)
{
    const float* x      = (const float*)d_in[0];
    const float* gamma  = (const float*)d_in[1];
    const float* beta   = (const float*)d_in[2];
    const float* w_qkv  = (const float*)d_in[3];
    const float* b_qkv  = (const float*)d_in[4];
    const float* w_proj = (const float*)d_in[5];
    const float* b_proj = (const float*)d_in[6];
    float* out = (float*)d_out;

    __half *ht, *qq, *kk, *vv, *pp, *ot, *wq, *wp;
    float *attn, *stats;
    cudaGetSymbolAddress((void**)&ht, g_ht);
    cudaGetSymbolAddress((void**)&qq, g_q );
    cudaGetSymbolAddress((void**)&kk, g_k );
    cudaGetSymbolAddress((void**)&vv, g_v );
    cudaGetSymbolAddress((void**)&pp, g_p );
    cudaGetSymbolAddress((void**)&ot, g_ot);
    cudaGetSymbolAddress((void**)&wq, g_wq);
    cudaGetSymbolAddress((void**)&wp, g_wp);
    cudaGetSymbolAddress((void**)&attn, g_attn);
    cudaGetSymbolAddress((void**)&stats, g_stats);

    cudaFuncSetAttribute(tc_gemm<0>, cudaFuncAttributeMaxDynamicSharedMemorySize, SMEM_BYTES);
    cudaFuncSetAttribute(tc_gemm<1>, cudaFuncAttributeMaxDynamicSharedMemorySize, SMEM_BYTES);
    cudaFuncSetAttribute(tc_gemm<2>, cudaFuncAttributeMaxDynamicSharedMemorySize, SMEM_BYTES);
    cudaFuncSetAttribute(tc_gemm<3>, cudaFuncAttributeMaxDynamicSharedMemorySize, SMEM_BYTES);

    const long long sH = (long long)NPIX * CH;
    const long long sP = (long long)NPIX * NPIX;

    pack_kernel<<<1024, 256>>>(w_qkv, wq, 3 * CH * CH, w_proj, wp, CH * CH);
    gn_stats_kernel<<<NB * NGRP, 256>>>(x, stats);
    gn_apply_kernel<<<dim3(NPIX / 32, CH / 32, NB), 256>>>(x, gamma, beta, stats, ht);

    // QKV: A = w_qkv, B = ht -> q [p][c], k [p][c], v [c][p]
    tc_gemm<0><<<dim3(NPIX / TN, 1536 / TM, NB), 256, SMEM_BYTES>>>(
        wq, ht, 0, sH, CH, CH, CH,
        b_qkv, 1.f, nullptr, qq, kk, vv, nullptr);

    // scores: A = q, B = k -> attn fp32
    tc_gemm<1><<<dim3(NPIX / TN, NPIX / TM, NB), 256, SMEM_BYTES>>>(
        qq, kk, sH, sH, CH, CH, CH,
        nullptr, 1.0f / sqrtf((float)CH), attn,
        nullptr, nullptr, nullptr, nullptr);

    softmax_kernel<<<NB * NPIX / 8, 256>>>(attn, pp);

    // PV: A = p, B = v -> ot [p][c]
    tc_gemm<2><<<dim3(CH / TN, NPIX / TM, NB), 256, SMEM_BYTES>>>(
        pp, vv, sP, sH, NPIX, NPIX, NPIX,
        nullptr, 1.f, nullptr, ot, nullptr, nullptr, nullptr);

    // proj: A = w_proj, B = ot + bias + residual -> out fp32
    tc_gemm<3><<<dim3(NPIX / TN, CH / TM, NB), 256, SMEM_BYTES>>>(
        wp, ot, 0, sH, CH, CH, CH,
        b_proj, 1.f, out, nullptr, nullptr, nullptr, x);
}

// round 15
// speedup vs baseline: 1.4695x; 1.4695x over previous
#include <cuda_runtime.h>
#include <cuda_fp16.h>
#include <math.h>
#include <stdint.h>

// ---------------------------------------------------------------------------
// Problem constants
// ---------------------------------------------------------------------------
constexpr int NB   = 16;
constexpr int CH   = 512;
constexpr int NPIX = 1024;
constexpr int NGRP = 32;

// GEMM tiling: CTA 128x128, BK=32, 8 warps (2M x 4N), warp tile 64x32
constexpr int TM = 128, TN = 128, TK = 32;

constexpr int A_STAGE     = 8192;                   // A: 128 rows * 64B
constexpr int B_STAGE     = 8192;                   // B: 128 rows * 64B
constexpr int STAGE_BYTES = A_STAGE + B_STAGE;      // 16384
constexpr int NSTAGE      = 4;                      // 65536 B of stages
constexpr int SPITCH      = 129;                    // fp32 epilogue pitch
constexpr int SMEM_BYTES  = TM * SPITCH * 4;        // 66048 (> 4*16384)

// ---------------------------------------------------------------------------
// Scratch (__device__ globals). All GEMM operands single fp16.
// ---------------------------------------------------------------------------
#define BALIGN __align__(256)
__device__ BALIGN __half g_ht[(size_t)NB * NPIX * CH];    // B of QKV   [b][p][c]
__device__ BALIGN __half g_q [(size_t)NB * NPIX * CH];    // A of scores[b][p][c]
__device__ BALIGN __half g_k [(size_t)NB * NPIX * CH];    // B of scores[b][p][c]
__device__ BALIGN __half g_v [(size_t)NB * CH * NPIX];    // B of PV    [b][c][p]
__device__ BALIGN __half g_p [(size_t)NB * NPIX * NPIX];  // A of PV    [b][i][j]
__device__ BALIGN __half g_ot[(size_t)NB * NPIX * CH];    // B of proj  [b][p][c]
__device__ BALIGN __half g_wq[(size_t)3 * CH * CH];       // A of QKV
__device__ BALIGN __half g_wp[(size_t)CH * CH];           // A of proj
__device__ BALIGN float  g_attn[(size_t)NB * NPIX * NPIX];
__device__ float g_stats[NB * NGRP * 2];

// ---------------------------------------------------------------------------
// helpers
// ---------------------------------------------------------------------------
__device__ __forceinline__ uint32_t smem_u32(const void* p) {
    uint32_t a;
    asm("{ .reg .u64 t; cvta.to.shared.u64 t, %1; cvt.u32.u64 %0, t; }" : "=r"(a) : "l"(p));
    return a;
}

#define CP16(sm, gp) asm volatile("cp.async.cg.shared.global [%0], [%1], 16;" :: "r"(sm), "l"(gp))
#define CP_COMMIT()  asm volatile("cp.async.commit_group;" ::: "memory")
#define CP_WAIT0()   asm volatile("cp.async.wait_group 0;" ::: "memory")
#define CP_WAIT2()   asm volatile("cp.async.wait_group 2;" ::: "memory")

#define LDSM4(r0, r1, r2, r3, a) \
    asm volatile("ldmatrix.sync.aligned.m8n8.x4.shared.b16 {%0,%1,%2,%3}, [%4];" \
                 : "=r"(r0), "=r"(r1), "=r"(r2), "=r"(r3) : "r"(a))

#define MMA_F16(d, a, b0, b1) \
    asm volatile("mma.sync.aligned.m16n8k16.row.col.f32.f16.f16.f32 " \
                 "{%0,%1,%2,%3},{%4,%5,%6,%7},{%8,%9},{%0,%1,%2,%3};" \
                 : "+f"((d)[0]), "+f"((d)[1]), "+f"((d)[2]), "+f"((d)[3]) \
                 : "r"((a)[0]), "r"((a)[1]), "r"((a)[2]), "r"((a)[3]), "r"(b0), "r"(b1))

// ---------------------------------------------------------------------------
// GroupNorm phase 1: per-(b,g) mean / rstd
// ---------------------------------------------------------------------------
__global__ __launch_bounds__(256) void gn_stats_kernel(
    const float* __restrict__ x, float* __restrict__ stats)
{
    const int GSZ = (CH / NGRP) * NPIX;
    const int bg  = blockIdx.x;
    const float4* xv = (const float4*)(x + (size_t)bg * GSZ);
    const int tid = threadIdx.x;

    float s = 0.f, ss = 0.f;
    for (int i = tid; i < GSZ / 4; i += 256) {
        float4 v = xv[i];
        s  += v.x + v.y + v.z + v.w;
        ss += v.x * v.x + v.y * v.y + v.z * v.z + v.w * v.w;
    }
    __shared__ float rs[256], rss[256];
    rs[tid] = s; rss[tid] = ss;
    __syncthreads();
    for (int o = 128; o > 0; o >>= 1) {
        if (tid < o) { rs[tid] += rs[tid + o]; rss[tid] += rss[tid + o]; }
        __syncthreads();
    }
    if (tid == 0) {
        float mu  = rs[0] / GSZ;
        float var = rss[0] / GSZ - mu * mu;
        stats[bg * 2]     = mu;
        stats[bg * 2 + 1] = rsqrtf(var + 1e-5f);
    }
}

// ---------------------------------------------------------------------------
// GroupNorm phase 2: normalize + transpose -> ht[b][p][c] (fp16)
// ---------------------------------------------------------------------------
__global__ __launch_bounds__(256) void gn_apply_kernel(
    const float* __restrict__ x, const float* __restrict__ gamma,
    const float* __restrict__ beta, const float* __restrict__ stats,
    __half* __restrict__ ht)
{
    __shared__ float s[32][33];
    const int p0 = blockIdx.x * 32, c0 = blockIdx.y * 32, b = blockIdx.z;
    const int tid = threadIdx.x;

    #pragma unroll
    for (int q = 0; q < 4; q++) {
        int ci = (tid >> 5) + q * 8, pj = tid & 31;
        int c = c0 + ci;
        float xv = x[((size_t)b * CH + c) * NPIX + p0 + pj];
        int g = c >> 4;
        float mu = stats[(b * NGRP + g) * 2], rinv = stats[(b * NGRP + g) * 2 + 1];
        s[ci][pj] = (xv - mu) * rinv * gamma[c] + beta[c];
    }
    __syncthreads();
    #pragma unroll
    for (int q = 0; q < 4; q++) {
        int cj = tid & 31, pi = (tid >> 5) + q * 8;
        size_t o = (size_t)b * NPIX * CH + (size_t)(p0 + pi) * CH + c0 + cj;
        ht[o] = __float2half(s[cj][pi]);
    }
}

// ---------------------------------------------------------------------------
// Row softmax -> fp16 P (block per row; proven R12 version)
// ---------------------------------------------------------------------------
__global__ __launch_bounds__(256) void softmax_kernel(
    const float* __restrict__ attn, __half* __restrict__ ph)
{
    const size_t row = blockIdx.x;
    const float4* p = (const float4*)(attn + row * NPIX);
    const int tid = threadIdx.x;
    const int lane = tid & 31, wrp = tid >> 5;
    __shared__ float red[8];

    float4 v = p[tid];
    float m = fmaxf(fmaxf(v.x, v.y), fmaxf(v.z, v.w));
    #pragma unroll
    for (int o = 16; o > 0; o >>= 1) m = fmaxf(m, __shfl_xor_sync(~0u, m, o));
    if (lane == 0) red[wrp] = m;
    __syncthreads();
    float rmax = red[0];
    #pragma unroll
    for (int w = 1; w < 8; w++) rmax = fmaxf(rmax, red[w]);
    __syncthreads();

    v.x = __expf(v.x - rmax); v.y = __expf(v.y - rmax);
    v.z = __expf(v.z - rmax); v.w = __expf(v.w - rmax);
    float s = v.x + v.y + v.z + v.w;
    #pragma unroll
    for (int o = 16; o > 0; o >>= 1) s += __shfl_xor_sync(~0u, s, o);
    if (lane == 0) red[wrp] = s;
    __syncthreads();
    float tot = red[0];
    #pragma unroll
    for (int w = 1; w < 8; w++) tot += red[w];

    const float rinv = 1.f / tot;
    size_t o = row * NPIX + tid * 4;
    *(__half2*)(ph + o)     = __half2(__float2half(v.x * rinv), __float2half(v.y * rinv));
    *(__half2*)(ph + o + 2) = __half2(__float2half(v.z * rinv), __float2half(v.w * rinv));
}

// ---------------------------------------------------------------------------
// fp32 -> fp16, both weight tensors in one grid-stride launch
// ---------------------------------------------------------------------------
__global__ __launch_bounds__(256) void pack_kernel(
    const float* __restrict__ w0, __half* __restrict__ o0, int n0,
    const float* __restrict__ w1, __half* __restrict__ o1, int n1)
{
    const int stride = gridDim.x * 256;
    for (int i = (blockIdx.x * 256 + threadIdx.x) * 2; i < n0; i += stride * 2)
        *(__half2*)(o0 + i) = __half2(__float2half(w0[i]), __float2half(w0[i + 1]));
    for (int i = (blockIdx.x * 256 + threadIdx.x) * 2; i < n1; i += stride * 2)
        *(__half2*)(o1 + i) = __half2(__float2half(w1[i]), __float2half(w1[i + 1]));
}

// ---------------------------------------------------------------------------
// fp16 HMMA GEMM: D[m][n] = sum_k A[m][k]*B[n][k] (both k-major, fp16).
// CTA 128x128, BK=32, 8 warps (2M x 4N), warp tile 64x32, 4-stage cp.async,
// one __syncthreads per k-iter, 2 CTAs/SM.
// smem rows 64B, 16B units XOR-swizzled by (row>>1)&3.
// Direct-register epilogue for row-major outputs (scores/PV/proj/V);
// smem-staged transpose only for Q/K.
// EPI 0: QKV  1: scores  2: PV  3: proj(+bias+residual)
// ---------------------------------------------------------------------------
template<int EPI>
__global__ __launch_bounds__(256, 2) void tc_gemm(
    const __half* __restrict__ Ag, const __half* __restrict__ Bg,
    long long sAb, long long sBb, int ldA, int ldB, int K,
    const float* __restrict__ bias, float scale,
    float* __restrict__ outf,
    __half* __restrict__ o0, __half* __restrict__ o1, __half* __restrict__ o2,
    const float* __restrict__ resid)
{
    extern __shared__ char smem[];
    const uint32_t sb = smem_u32(smem);
    const int tid = threadIdx.x;
    const int lane = tid & 31, wid = tid >> 5;
    const int bz = blockIdx.z;
    const int m0 = blockIdx.y * TM;
    const int n0 = blockIdx.x * TN;

    const __half* Ap = Ag + (size_t)bz * sAb + (size_t)m0 * ldA;
    const __half* Bp = Bg + (size_t)bz * sBb + (size_t)n0 * ldB;

    // loaders: row = tid>>1 (0..127), 2 of 4 16B units each
    const int lrow = tid >> 1;
    const int usel = tid & 1;

    auto load_tile = [&](int buf, int k0) {
        const uint32_t sa  = sb + buf * STAGE_BYTES;
        const uint32_t sbB = sa + A_STAGE;
        const int rsw = (lrow >> 1) & 3;
        #pragma unroll
        for (int j = 0; j < 2; j++) {
            const int u = usel * 2 + j;
            const uint32_t sw = (uint32_t)((u ^ rsw) << 4);
            CP16(sa  + lrow * 64 + sw, Ap + (size_t)lrow * ldA + k0 + u * 8);
            CP16(sbB + lrow * 64 + sw, Bp + (size_t)lrow * ldB + k0 + u * 8);
        }
    };

    // warp layout: 2 (M) x 4 (N), warp tile 64x32
    const int wm = wid >> 2, wn = wid & 3;
    const int m_base = wm * 64, n_base = wn * 32;

    // ldmatrix lane mapping
    const int amat = lane >> 3;
    const int arow = (amat & 1) * 8 + (lane & 7);
    const int auadd = amat >> 1;
    const int bmat = lane >> 3;
    const int bnrow = (bmat >> 1) * 8 + (lane & 7);
    const int buadd = bmat & 1;

    float acc[4][4][4] = {};

    const int nk = K / TK;
    load_tile(0, 0);
    CP_COMMIT();
    load_tile(1, TK);
    CP_COMMIT();
    load_tile(2, 2 * TK);
    CP_COMMIT();

    for (int i = 0; i < nk; i++) {
        if (i == nk - 1) { CP_WAIT0(); } else { CP_WAIT2(); }
        __syncthreads();
        if (i + 3 < nk) {
            load_tile((i + 3) % NSTAGE, (i + 3) * TK);
            CP_COMMIT();
        }
        const uint32_t sa  = sb + (i % NSTAGE) * STAGE_BYTES;
        const uint32_t sbB = sa + A_STAGE;

        #pragma unroll
        for (int kk = 0; kk < 2; kk++) {
            uint32_t bh[8];
            #pragma unroll
            for (int np = 0; np < 2; np++) {
                const int n = n_base + np * 16 + bnrow;
                const int uh = kk * 2 + buadd;
                LDSM4(bh[np * 4 + 0], bh[np * 4 + 1], bh[np * 4 + 2], bh[np * 4 + 3],
                      sbB + n * 64 + ((uh ^ ((n >> 1) & 3)) << 4));
            }
            uint32_t ah[4][4];
            #pragma unroll
            for (int mt = 0; mt < 4; mt++) {
                const int row = m_base + mt * 16 + arow;
                const int uh = kk * 2 + auadd;
                LDSM4(ah[mt][0], ah[mt][1], ah[mt][2], ah[mt][3],
                      sa + row * 64 + ((uh ^ ((row >> 1) & 3)) << 4));
            }
            #pragma unroll
            for (int mt = 0; mt < 4; mt++)
                #pragma unroll
                for (int nt = 0; nt < 4; nt++) {
                    const int r = (nt >> 1) * 4 + (nt & 1) * 2;
                    MMA_F16(acc[mt][nt], ah[mt], bh[r], bh[r + 1]);
                }
        }
    }

    // ---- epilogues ----
    const int rowL = lane >> 2;            // 0..7
    const int colL = (lane & 3) * 2;       // 0..6

    if (EPI == 0 && m0 < 2 * CH) {
        // Q or K tile: needs transpose -> smem staging
        __syncthreads();
        float* s = (float*)smem;
        #pragma unroll
        for (int mt = 0; mt < 4; mt++)
            #pragma unroll
            for (int nt = 0; nt < 4; nt++)
                #pragma unroll
                for (int r = 0; r < 4; r++) {
                    const int row = m_base + mt * 16 + rowL + (r >= 2 ? 8 : 0);
                    const int col = n_base + nt * 8 + colL + (r & 1);
                    s[row * SPITCH + col] = acc[mt][nt][r];
                }
        __syncthreads();
        __half* d = (m0 < CH ? o0 : o1) + (size_t)bz * NPIX * CH;
        const int coff = m0 & (CH - 1);
        for (int it = 0; it < 32; it++) {
            const int idx = it * 512 + tid * 2;
            const int n = idx >> 7, m = idx & 127;
            float v0 = s[m * SPITCH + n] + bias[m0 + m];
            float v1 = s[(m + 1) * SPITCH + n] + bias[m0 + m + 1];
            const size_t o = (size_t)(n0 + n) * CH + coff + m;
            *(__half2*)(d + o) = __half2(__float2half(v0), __float2half(v1));
        }
    } else {
        // direct-register writers: acc pairs are adjacent output columns
        #pragma unroll
        for (int mt = 0; mt < 4; mt++) {
            #pragma unroll
            for (int nt = 0; nt < 4; nt++) {
                const int col = n_base + nt * 8 + colL;
                #pragma unroll
                for (int h = 0; h < 2; h++) {       // h=0: rows+0, h=1: rows+8
                    const int row = m_base + mt * 16 + rowL + h * 8;
                    const float a0 = acc[mt][nt][h * 2];
                    const float a1 = acc[mt][nt][h * 2 + 1];
                    if (EPI == 0) {          // V tile -> v[b][c][p] fp16 (+bias)
                        const int c = m0 - 2 * CH + row;
                        const float bv = bias[m0 + row];
                        const size_t o = ((size_t)bz * CH + c) * NPIX + n0 + col;
                        *(__half2*)(o2 + o) =
                            __half2(__float2half(a0 + bv), __float2half(a1 + bv));
                    } else if (EPI == 1) {   // scores fp32 * scale
                        const size_t o = ((size_t)bz * NPIX + m0 + row) * NPIX + n0 + col;
                        *(float2*)(outf + o) = make_float2(a0 * scale, a1 * scale);
                    } else if (EPI == 2) {   // Ot fp16 [p][c]
                        const size_t o = ((size_t)bz * NPIX + m0 + row) * CH + n0 + col;
                        *(__half2*)(o0 + o) =
                            __half2(__float2half(a0), __float2half(a1));
                    } else {                 // proj + bias + residual fp32
                        const float bv = bias[m0 + row];
                        const size_t o = ((size_t)bz * CH + m0 + row) * NPIX + n0 + col;
                        float2 rv = *(const float2*)(resid + o);
                        *(float2*)(outf + o) =
                            make_float2(a0 + bv + rv.x, a1 + bv + rv.y);
                    }
                }
            }
        }
    }
}

// ---------------------------------------------------------------------------
extern "C" void kernel_launch(void* const* d_in, const int* in_sizes, int n_in,
                              void* d_out, int out_size)
{
    const float* x      = (const float*)d_in[0];
    const float* gamma  = (const float*)d_in[1];
    const float* beta   = (const float*)d_in[2];
    const float* w_qkv  = (const float*)d_in[3];
    const float* b_qkv  = (const float*)d_in[4];
    const float* w_proj = (const float*)d_in[5];
    const float* b_proj = (const float*)d_in[6];
    float* out = (float*)d_out;

    __half *ht, *qq, *kk, *vv, *pp, *ot, *wq, *wp;
    float *attn, *stats;
    cudaGetSymbolAddress((void**)&ht, g_ht);
    cudaGetSymbolAddress((void**)&qq, g_q );
    cudaGetSymbolAddress((void**)&kk, g_k );
    cudaGetSymbolAddress((void**)&vv, g_v );
    cudaGetSymbolAddress((void**)&pp, g_p );
    cudaGetSymbolAddress((void**)&ot, g_ot);
    cudaGetSymbolAddress((void**)&wq, g_wq);
    cudaGetSymbolAddress((void**)&wp, g_wp);
    cudaGetSymbolAddress((void**)&attn, g_attn);
    cudaGetSymbolAddress((void**)&stats, g_stats);

    cudaFuncSetAttribute(tc_gemm<0>, cudaFuncAttributeMaxDynamicSharedMemorySize, SMEM_BYTES);
    cudaFuncSetAttribute(tc_gemm<1>, cudaFuncAttributeMaxDynamicSharedMemorySize, SMEM_BYTES);
    cudaFuncSetAttribute(tc_gemm<2>, cudaFuncAttributeMaxDynamicSharedMemorySize, SMEM_BYTES);
    cudaFuncSetAttribute(tc_gemm<3>, cudaFuncAttributeMaxDynamicSharedMemorySize, SMEM_BYTES);

    const long long sH = (long long)NPIX * CH;
    const long long sP = (long long)NPIX * NPIX;

    pack_kernel<<<1024, 256>>>(w_qkv, wq, 3 * CH * CH, w_proj, wp, CH * CH);
    gn_stats_kernel<<<NB * NGRP, 256>>>(x, stats);
    gn_apply_kernel<<<dim3(NPIX / 32, CH / 32, NB), 256>>>(x, gamma, beta, stats, ht);

    // QKV: A = w_qkv, B = ht -> q [p][c], k [p][c], v [c][p]
    tc_gemm<0><<<dim3(NPIX / TN, 1536 / TM, NB), 256, SMEM_BYTES>>>(
        wq, ht, 0, sH, CH, CH, CH,
        b_qkv, 1.f, nullptr, qq, kk, vv, nullptr);

    // scores: A = q, B = k -> attn fp32
    tc_gemm<1><<<dim3(NPIX / TN, NPIX / TM, NB), 256, SMEM_BYTES>>>(
        qq, kk, sH, sH, CH, CH, CH,
        nullptr, 1.0f / sqrtf((float)CH), attn,
        nullptr, nullptr, nullptr, nullptr);

    softmax_kernel<<<NB * NPIX, 256>>>(attn, pp);

    // PV: A = p, B = v -> ot [p][c]
    tc_gemm<2><<<dim3(CH / TN, NPIX / TM, NB), 256, SMEM_BYTES>>>(
        pp, vv, sP, sH, NPIX, NPIX, NPIX,
        nullptr, 1.f, nullptr, ot, nullptr, nullptr, nullptr);

    // proj: A = w_proj, B = ot + bias + residual -> out fp32
    tc_gemm<3><<<dim3(NPIX / TN, CH / TM, NB), 256, SMEM_BYTES>>>(
        wp, ot, 0, sH, CH, CH, CH,
        b_proj, 1.f, out, nullptr, nullptr, nullptr, x);
}

// round 16
// speedup vs baseline: 1.4999x; 1.0207x over previous
#include <cuda_runtime.h>
#include <cuda_fp16.h>
#include <math.h>
#include <stdint.h>

// ---------------------------------------------------------------------------
// Problem constants
// ---------------------------------------------------------------------------
constexpr int NB   = 16;
constexpr int CH   = 512;
constexpr int NPIX = 1024;
constexpr int NGRP = 32;

// GEMM tiling: CTA 128x128, BK=32, 8 warps (2M x 4N), warp tile 64x32
constexpr int TM = 128, TN = 128, TK = 32;

constexpr int A_STAGE     = 8192;                   // A: 128 rows * 64B
constexpr int B_STAGE     = 8192;                   // B: 128 rows * 64B
constexpr int STAGE_BYTES = A_STAGE + B_STAGE;      // 16384
constexpr int NSTAGE      = 4;                      // 65536 B of stages
constexpr int SPITCH      = 129;                    // fp32 epilogue pitch
constexpr int SMEM_BYTES  = TM * SPITCH * 4;        // 66048 (> 4*16384)

// ---------------------------------------------------------------------------
// Scratch (__device__ globals). All GEMM operands single fp16.
// ---------------------------------------------------------------------------
#define BALIGN __align__(256)
__device__ BALIGN __half g_ht[(size_t)NB * NPIX * CH];    // B of QKV   [b][p][c]
__device__ BALIGN __half g_q [(size_t)NB * NPIX * CH];    // A of scores[b][p][c]
__device__ BALIGN __half g_k [(size_t)NB * NPIX * CH];    // B of scores[b][p][c]
__device__ BALIGN __half g_v [(size_t)NB * CH * NPIX];    // B of PV    [b][c][p]
__device__ BALIGN __half g_p [(size_t)NB * NPIX * NPIX];  // A of PV    [b][i][j]
__device__ BALIGN __half g_ot[(size_t)NB * NPIX * CH];    // B of proj  [b][p][c]
__device__ BALIGN __half g_wq[(size_t)3 * CH * CH];       // A of QKV
__device__ BALIGN __half g_wp[(size_t)CH * CH];           // A of proj
__device__ BALIGN float  g_attn[(size_t)NB * NPIX * NPIX];
__device__ float g_stats[NB * NGRP * 2];

// ---------------------------------------------------------------------------
// helpers
// ---------------------------------------------------------------------------
__device__ __forceinline__ uint32_t smem_u32(const void* p) {
    uint32_t a;
    asm("{ .reg .u64 t; cvta.to.shared.u64 t, %1; cvt.u32.u64 %0, t; }" : "=r"(a) : "l"(p));
    return a;
}

#define CP16(sm, gp) asm volatile("cp.async.cg.shared.global [%0], [%1], 16;" :: "r"(sm), "l"(gp))
#define CP_COMMIT()  asm volatile("cp.async.commit_group;" ::: "memory")
#define CP_WAIT0()   asm volatile("cp.async.wait_group 0;" ::: "memory")
#define CP_WAIT2()   asm volatile("cp.async.wait_group 2;" ::: "memory")

#define LDSM4(r0, r1, r2, r3, a) \
    asm volatile("ldmatrix.sync.aligned.m8n8.x4.shared.b16 {%0,%1,%2,%3}, [%4];" \
                 : "=r"(r0), "=r"(r1), "=r"(r2), "=r"(r3) : "r"(a))

#define MMA_F16(d, a, b0, b1) \
    asm volatile("mma.sync.aligned.m16n8k16.row.col.f32.f16.f16.f32 " \
                 "{%0,%1,%2,%3},{%4,%5,%6,%7},{%8,%9},{%0,%1,%2,%3};" \
                 : "+f"((d)[0]), "+f"((d)[1]), "+f"((d)[2]), "+f"((d)[3]) \
                 : "r"((a)[0]), "r"((a)[1]), "r"((a)[2]), "r"((a)[3]), "r"(b0), "r"(b1))

// ---------------------------------------------------------------------------
// GroupNorm phase 1: per-(b,g) mean / rstd
// ---------------------------------------------------------------------------
__global__ __launch_bounds__(256) void gn_stats_kernel(
    const float* __restrict__ x, float* __restrict__ stats)
{
    const int GSZ = (CH / NGRP) * NPIX;
    const int bg  = blockIdx.x;
    const float4* xv = (const float4*)(x + (size_t)bg * GSZ);
    const int tid = threadIdx.x;

    float s = 0.f, ss = 0.f;
    for (int i = tid; i < GSZ / 4; i += 256) {
        float4 v = xv[i];
        s  += v.x + v.y + v.z + v.w;
        ss += v.x * v.x + v.y * v.y + v.z * v.z + v.w * v.w;
    }
    __shared__ float rs[256], rss[256];
    rs[tid] = s; rss[tid] = ss;
    __syncthreads();
    for (int o = 128; o > 0; o >>= 1) {
        if (tid < o) { rs[tid] += rs[tid + o]; rss[tid] += rss[tid + o]; }
        __syncthreads();
    }
    if (tid == 0) {
        float mu  = rs[0] / GSZ;
        float var = rss[0] / GSZ - mu * mu;
        stats[bg * 2]     = mu;
        stats[bg * 2 + 1] = rsqrtf(var + 1e-5f);
    }
}

// ---------------------------------------------------------------------------
// GroupNorm phase 2: normalize + transpose -> ht[b][p][c] (fp16)
// ---------------------------------------------------------------------------
__global__ __launch_bounds__(256) void gn_apply_kernel(
    const float* __restrict__ x, const float* __restrict__ gamma,
    const float* __restrict__ beta, const float* __restrict__ stats,
    __half* __restrict__ ht)
{
    __shared__ float s[32][33];
    const int p0 = blockIdx.x * 32, c0 = blockIdx.y * 32, b = blockIdx.z;
    const int tid = threadIdx.x;

    #pragma unroll
    for (int q = 0; q < 4; q++) {
        int ci = (tid >> 5) + q * 8, pj = tid & 31;
        int c = c0 + ci;
        float xv = x[((size_t)b * CH + c) * NPIX + p0 + pj];
        int g = c >> 4;
        float mu = stats[(b * NGRP + g) * 2], rinv = stats[(b * NGRP + g) * 2 + 1];
        s[ci][pj] = (xv - mu) * rinv * gamma[c] + beta[c];
    }
    __syncthreads();
    #pragma unroll
    for (int q = 0; q < 4; q++) {
        int cj = tid & 31, pi = (tid >> 5) + q * 8;
        size_t o = (size_t)b * NPIX * CH + (size_t)(p0 + pi) * CH + c0 + cj;
        ht[o] = __float2half(s[cj][pi]);
    }
}

// ---------------------------------------------------------------------------
// Row softmax -> fp16 P. 2 rows per 256-thread block: each 128-thread half
// owns one row (2 x float4 per thread, MLP=2). Reductions: warp shfl ->
// per-warp smem slot -> scan of own half's 4 slots. Two block barriers.
// ---------------------------------------------------------------------------
__global__ __launch_bounds__(256) void softmax_kernel(
    const float* __restrict__ attn, __half* __restrict__ ph)
{
    const int tid  = threadIdx.x;
    const int half = tid >> 7;                 // 0 or 1
    const int t    = tid & 127;
    const int lane = tid & 31, wrp = tid >> 5; // 0..7
    const size_t row = (size_t)blockIdx.x * 2 + half;

    const float4* p = (const float4*)(attn + row * NPIX);
    float4 v0 = p[t];
    float4 v1 = p[t + 128];

    __shared__ float redm[8], reds[8];

    float m = fmaxf(fmaxf(fmaxf(v0.x, v0.y), fmaxf(v0.z, v0.w)),
                    fmaxf(fmaxf(v1.x, v1.y), fmaxf(v1.z, v1.w)));
    #pragma unroll
    for (int o = 16; o > 0; o >>= 1) m = fmaxf(m, __shfl_xor_sync(~0u, m, o));
    if (lane == 0) redm[wrp] = m;
    __syncthreads();
    float rmax = redm[half * 4];
    #pragma unroll
    for (int w = 1; w < 4; w++) rmax = fmaxf(rmax, redm[half * 4 + w]);

    v0.x = __expf(v0.x - rmax); v0.y = __expf(v0.y - rmax);
    v0.z = __expf(v0.z - rmax); v0.w = __expf(v0.w - rmax);
    v1.x = __expf(v1.x - rmax); v1.y = __expf(v1.y - rmax);
    v1.z = __expf(v1.z - rmax); v1.w = __expf(v1.w - rmax);
    float s = v0.x + v0.y + v0.z + v0.w + v1.x + v1.y + v1.z + v1.w;
    #pragma unroll
    for (int o = 16; o > 0; o >>= 1) s += __shfl_xor_sync(~0u, s, o);
    if (lane == 0) reds[wrp] = s;
    __syncthreads();
    float tot = reds[half * 4];
    #pragma unroll
    for (int w = 1; w < 4; w++) tot += reds[half * 4 + w];

    const float rinv = 1.f / tot;
    uint2* po = (uint2*)(ph + row * NPIX);
    __half2 h0(__float2half(v0.x * rinv), __float2half(v0.y * rinv));
    __half2 h1(__float2half(v0.z * rinv), __float2half(v0.w * rinv));
    uint2 u0; u0.x = *(uint32_t*)&h0; u0.y = *(uint32_t*)&h1;
    po[t] = u0;
    __half2 h2(__float2half(v1.x * rinv), __float2half(v1.y * rinv));
    __half2 h3(__float2half(v1.z * rinv), __float2half(v1.w * rinv));
    uint2 u1; u1.x = *(uint32_t*)&h2; u1.y = *(uint32_t*)&h3;
    po[t + 128] = u1;
}

// ---------------------------------------------------------------------------
// fp32 -> fp16, both weight tensors in one grid-stride launch
// ---------------------------------------------------------------------------
__global__ __launch_bounds__(256) void pack_kernel(
    const float* __restrict__ w0, __half* __restrict__ o0, int n0,
    const float* __restrict__ w1, __half* __restrict__ o1, int n1)
{
    const int stride = gridDim.x * 256;
    for (int i = (blockIdx.x * 256 + threadIdx.x) * 2; i < n0; i += stride * 2)
        *(__half2*)(o0 + i) = __half2(__float2half(w0[i]), __float2half(w0[i + 1]));
    for (int i = (blockIdx.x * 256 + threadIdx.x) * 2; i < n1; i += stride * 2)
        *(__half2*)(o1 + i) = __half2(__float2half(w1[i]), __float2half(w1[i + 1]));
}

// ---------------------------------------------------------------------------
// fp16 HMMA GEMM: D[m][n] = sum_k A[m][k]*B[n][k] (both k-major, fp16).
// CTA 128x128, BK=32, 8 warps (2M x 4N), warp tile 64x32, 4-stage cp.async,
// one __syncthreads per k-iter, 2 CTAs/SM.
// smem rows 64B, 16B units XOR-swizzled by (row>>1)&3.
// Direct-register epilogue for row-major outputs (scores/PV/proj/V);
// smem-staged transpose only for Q/K.
// EPI 0: QKV  1: scores  2: PV  3: proj(+bias+residual)
// ---------------------------------------------------------------------------
template<int EPI>
__global__ __launch_bounds__(256, 2) void tc_gemm(
    const __half* __restrict__ Ag, const __half* __restrict__ Bg,
    long long sAb, long long sBb, int ldA, int ldB, int K,
    const float* __restrict__ bias, float scale,
    float* __restrict__ outf,
    __half* __restrict__ o0, __half* __restrict__ o1, __half* __restrict__ o2,
    const float* __restrict__ resid)
{
    extern __shared__ char smem[];
    const uint32_t sb = smem_u32(smem);
    const int tid = threadIdx.x;
    const int lane = tid & 31, wid = tid >> 5;
    const int bz = blockIdx.z;
    const int m0 = blockIdx.y * TM;
    const int n0 = blockIdx.x * TN;

    const __half* Ap = Ag + (size_t)bz * sAb + (size_t)m0 * ldA;
    const __half* Bp = Bg + (size_t)bz * sBb + (size_t)n0 * ldB;

    // loaders: row = tid>>1 (0..127), 2 of 4 16B units each
    const int lrow = tid >> 1;
    const int usel = tid & 1;

    auto load_tile = [&](int buf, int k0) {
        const uint32_t sa  = sb + buf * STAGE_BYTES;
        const uint32_t sbB = sa + A_STAGE;
        const int rsw = (lrow >> 1) & 3;
        #pragma unroll
        for (int j = 0; j < 2; j++) {
            const int u = usel * 2 + j;
            const uint32_t sw = (uint32_t)((u ^ rsw) << 4);
            CP16(sa  + lrow * 64 + sw, Ap + (size_t)lrow * ldA + k0 + u * 8);
            CP16(sbB + lrow * 64 + sw, Bp + (size_t)lrow * ldB + k0 + u * 8);
        }
    };

    // warp layout: 2 (M) x 4 (N), warp tile 64x32
    const int wm = wid >> 2, wn = wid & 3;
    const int m_base = wm * 64, n_base = wn * 32;

    // ldmatrix lane mapping
    const int amat = lane >> 3;
    const int arow = (amat & 1) * 8 + (lane & 7);
    const int auadd = amat >> 1;
    const int bmat = lane >> 3;
    const int bnrow = (bmat >> 1) * 8 + (lane & 7);
    const int buadd = bmat & 1;

    float acc[4][4][4] = {};

    const int nk = K / TK;
    load_tile(0, 0);
    CP_COMMIT();
    load_tile(1, TK);
    CP_COMMIT();
    load_tile(2, 2 * TK);
    CP_COMMIT();

    for (int i = 0; i < nk; i++) {
        if (i == nk - 1) { CP_WAIT0(); } else { CP_WAIT2(); }
        __syncthreads();
        if (i + 3 < nk) {
            load_tile((i + 3) % NSTAGE, (i + 3) * TK);
            CP_COMMIT();
        }
        const uint32_t sa  = sb + (i % NSTAGE) * STAGE_BYTES;
        const uint32_t sbB = sa + A_STAGE;

        #pragma unroll
        for (int kk = 0; kk < 2; kk++) {
            uint32_t bh[8];
            #pragma unroll
            for (int np = 0; np < 2; np++) {
                const int n = n_base + np * 16 + bnrow;
                const int uh = kk * 2 + buadd;
                LDSM4(bh[np * 4 + 0], bh[np * 4 + 1], bh[np * 4 + 2], bh[np * 4 + 3],
                      sbB + n * 64 + ((uh ^ ((n >> 1) & 3)) << 4));
            }
            uint32_t ah[4][4];
            #pragma unroll
            for (int mt = 0; mt < 4; mt++) {
                const int row = m_base + mt * 16 + arow;
                const int uh = kk * 2 + auadd;
                LDSM4(ah[mt][0], ah[mt][1], ah[mt][2], ah[mt][3],
                      sa + row * 64 + ((uh ^ ((row >> 1) & 3)) << 4));
            }
            #pragma unroll
            for (int mt = 0; mt < 4; mt++)
                #pragma unroll
                for (int nt = 0; nt < 4; nt++) {
                    const int r = (nt >> 1) * 4 + (nt & 1) * 2;
                    MMA_F16(acc[mt][nt], ah[mt], bh[r], bh[r + 1]);
                }
        }
    }

    // ---- epilogues ----
    const int rowL = lane >> 2;            // 0..7
    const int colL = (lane & 3) * 2;       // 0..6

    if (EPI == 0 && m0 < 2 * CH) {
        // Q or K tile: needs transpose -> smem staging
        __syncthreads();
        float* s = (float*)smem;
        #pragma unroll
        for (int mt = 0; mt < 4; mt++)
            #pragma unroll
            for (int nt = 0; nt < 4; nt++)
                #pragma unroll
                for (int r = 0; r < 4; r++) {
                    const int row = m_base + mt * 16 + rowL + (r >= 2 ? 8 : 0);
                    const int col = n_base + nt * 8 + colL + (r & 1);
                    s[row * SPITCH + col] = acc[mt][nt][r];
                }
        __syncthreads();
        __half* d = (m0 < CH ? o0 : o1) + (size_t)bz * NPIX * CH;
        const int coff = m0 & (CH - 1);
        for (int it = 0; it < 32; it++) {
            const int idx = it * 512 + tid * 2;
            const int n = idx >> 7, m = idx & 127;
            float v0 = s[m * SPITCH + n] + bias[m0 + m];
            float v1 = s[(m + 1) * SPITCH + n] + bias[m0 + m + 1];
            const size_t o = (size_t)(n0 + n) * CH + coff + m;
            *(__half2*)(d + o) = __half2(__float2half(v0), __float2half(v1));
        }
    } else {
        // direct-register writers: acc pairs are adjacent output columns
        #pragma unroll
        for (int mt = 0; mt < 4; mt++) {
            #pragma unroll
            for (int nt = 0; nt < 4; nt++) {
                const int col = n_base + nt * 8 + colL;
                #pragma unroll
                for (int h = 0; h < 2; h++) {       // h=0: rows+0, h=1: rows+8
                    const int row = m_base + mt * 16 + rowL + h * 8;
                    const float a0 = acc[mt][nt][h * 2];
                    const float a1 = acc[mt][nt][h * 2 + 1];
                    if (EPI == 0) {          // V tile -> v[b][c][p] fp16 (+bias)
                        const int c = m0 - 2 * CH + row;
                        const float bv = bias[m0 + row];
                        const size_t o = ((size_t)bz * CH + c) * NPIX + n0 + col;
                        *(__half2*)(o2 + o) =
                            __half2(__float2half(a0 + bv), __float2half(a1 + bv));
                    } else if (EPI == 1) {   // scores fp32 * scale
                        const size_t o = ((size_t)bz * NPIX + m0 + row) * NPIX + n0 + col;
                        *(float2*)(outf + o) = make_float2(a0 * scale, a1 * scale);
                    } else if (EPI == 2) {   // Ot fp16 [p][c]
                        const size_t o = ((size_t)bz * NPIX + m0 + row) * CH + n0 + col;
                        *(__half2*)(o0 + o) =
                            __half2(__float2half(a0), __float2half(a1));
                    } else {                 // proj + bias + residual fp32
                        const float bv = bias[m0 + row];
                        const size_t o = ((size_t)bz * CH + m0 + row) * NPIX + n0 + col;
                        float2 rv = *(const float2*)(resid + o);
                        *(float2*)(outf + o) =
                            make_float2(a0 + bv + rv.x, a1 + bv + rv.y);
                    }
                }
            }
        }
    }
}

// ---------------------------------------------------------------------------
extern "C" void kernel_launch(void* const* d_in, const int* in_sizes, int n_in,
                              void* d_out, int out_size)
{
    const float* x      = (const float*)d_in[0];
    const float* gamma  = (const float*)d_in[1];
    const float* beta   = (const float*)d_in[2];
    const float* w_qkv  = (const float*)d_in[3];
    const float* b_qkv  = (const float*)d_in[4];
    const float* w_proj = (const float*)d_in[5];
    const float* b_proj = (const float*)d_in[6];
    float* out = (float*)d_out;

    __half *ht, *qq, *kk, *vv, *pp, *ot, *wq, *wp;
    float *attn, *stats;
    cudaGetSymbolAddress((void**)&ht, g_ht);
    cudaGetSymbolAddress((void**)&qq, g_q );
    cudaGetSymbolAddress((void**)&kk, g_k );
    cudaGetSymbolAddress((void**)&vv, g_v );
    cudaGetSymbolAddress((void**)&pp, g_p );
    cudaGetSymbolAddress((void**)&ot, g_ot);
    cudaGetSymbolAddress((void**)&wq, g_wq);
    cudaGetSymbolAddress((void**)&wp, g_wp);
    cudaGetSymbolAddress((void**)&attn, g_attn);
    cudaGetSymbolAddress((void**)&stats, g_stats);

    cudaFuncSetAttribute(tc_gemm<0>, cudaFuncAttributeMaxDynamicSharedMemorySize, SMEM_BYTES);
    cudaFuncSetAttribute(tc_gemm<1>, cudaFuncAttributeMaxDynamicSharedMemorySize, SMEM_BYTES);
    cudaFuncSetAttribute(tc_gemm<2>, cudaFuncAttributeMaxDynamicSharedMemorySize, SMEM_BYTES);
    cudaFuncSetAttribute(tc_gemm<3>, cudaFuncAttributeMaxDynamicSharedMemorySize, SMEM_BYTES);

    const long long sH = (long long)NPIX * CH;
    const long long sP = (long long)NPIX * NPIX;

    pack_kernel<<<1024, 256>>>(w_qkv, wq, 3 * CH * CH, w_proj, wp, CH * CH);
    gn_stats_kernel<<<NB * NGRP, 256>>>(x, stats);
    gn_apply_kernel<<<dim3(NPIX / 32, CH / 32, NB), 256>>>(x, gamma, beta, stats, ht);

    // QKV: A = w_qkv, B = ht -> q [p][c], k [p][c], v [c][p]
    tc_gemm<0><<<dim3(NPIX / TN, 1536 / TM, NB), 256, SMEM_BYTES>>>(
        wq, ht, 0, sH, CH, CH, CH,
        b_qkv, 1.f, nullptr, qq, kk, vv, nullptr);

    // scores: A = q, B = k -> attn fp32
    tc_gemm<1><<<dim3(NPIX / TN, NPIX / TM, NB), 256, SMEM_BYTES>>>(
        qq, kk, sH, sH, CH, CH, CH,
        nullptr, 1.0f / sqrtf((float)CH), attn,
        nullptr, nullptr, nullptr, nullptr);

    softmax_kernel<<<NB * NPIX / 2, 256>>>(attn, pp);

    // PV: A = p, B = v -> ot [p][c]
    tc_gemm<2><<<dim3(CH / TN, NPIX / TM, NB), 256, SMEM_BYTES>>>(
        pp, vv, sP, sH, NPIX, NPIX, NPIX,
        nullptr, 1.f, nullptr, ot, nullptr, nullptr, nullptr);

    // proj: A = w_proj, B = ot + bias + residual -> out fp32
    tc_gemm<3><<<dim3(NPIX / TN, CH / TM, NB), 256, SMEM_BYTES>>>(
        wp, ot, 0, sH, CH, CH, CH,
        b_proj, 1.f, out, nullptr, nullptr, nullptr, x);
}

// round 17
// speedup vs baseline: 1.5164x; 1.0110x over previous
#include <cuda_runtime.h>
#include <cuda_fp16.h>
#include <math.h>
#include <stdint.h>

// ---------------------------------------------------------------------------
// Problem constants
// ---------------------------------------------------------------------------
constexpr int NB   = 16;
constexpr int CH   = 512;
constexpr int NPIX = 1024;
constexpr int NGRP = 32;

// GEMM tiling: CTA 128x128, BK=32, 8 warps (2M x 4N), warp tile 64x32
constexpr int TM = 128, TN = 128, TK = 32;

constexpr int A_STAGE     = 8192;                   // A: 128 rows * 64B
constexpr int B_STAGE     = 8192;                   // B: 128 rows * 64B
constexpr int STAGE_BYTES = A_STAGE + B_STAGE;      // 16384
constexpr int NSTAGE      = 4;                      // 65536 B of stages
constexpr int SPITCH      = 129;                    // fp32 epilogue pitch
constexpr int SMEM_BYTES  = TM * SPITCH * 4;        // 66048 (> 4*16384)

// ---------------------------------------------------------------------------
// Scratch (__device__ globals). All GEMM operands single fp16.
// ---------------------------------------------------------------------------
#define BALIGN __align__(256)
__device__ BALIGN __half g_ht[(size_t)NB * NPIX * CH];    // B of QKV   [b][p][c]
__device__ BALIGN __half g_q [(size_t)NB * NPIX * CH];    // A of scores[b][p][c]
__device__ BALIGN __half g_k [(size_t)NB * NPIX * CH];    // B of scores[b][p][c]
__device__ BALIGN __half g_v [(size_t)NB * CH * NPIX];    // B of PV    [b][c][p]
__device__ BALIGN __half g_p [(size_t)NB * NPIX * NPIX];  // A of PV    [b][i][j]
__device__ BALIGN __half g_ot[(size_t)NB * NPIX * CH];    // B of proj  [b][p][c]
__device__ BALIGN __half g_wq[(size_t)3 * CH * CH];       // A of QKV
__device__ BALIGN __half g_wp[(size_t)CH * CH];           // A of proj
__device__ BALIGN float  g_attn[(size_t)NB * NPIX * NPIX];
__device__ float g_stats[NB * NGRP * 2];

// ---------------------------------------------------------------------------
// helpers
// ---------------------------------------------------------------------------
__device__ __forceinline__ uint32_t smem_u32(const void* p) {
    uint32_t a;
    asm("{ .reg .u64 t; cvta.to.shared.u64 t, %1; cvt.u32.u64 %0, t; }" : "=r"(a) : "l"(p));
    return a;
}

#define CP16(sm, gp) asm volatile("cp.async.cg.shared.global [%0], [%1], 16;" :: "r"(sm), "l"(gp))
#define CP_COMMIT()  asm volatile("cp.async.commit_group;" ::: "memory")
#define CP_WAIT0()   asm volatile("cp.async.wait_group 0;" ::: "memory")
#define CP_WAIT2()   asm volatile("cp.async.wait_group 2;" ::: "memory")

#define LDSM4(r0, r1, r2, r3, a) \
    asm volatile("ldmatrix.sync.aligned.m8n8.x4.shared.b16 {%0,%1,%2,%3}, [%4];" \
                 : "=r"(r0), "=r"(r1), "=r"(r2), "=r"(r3) : "r"(a))

#define MMA_F16(d, a, b0, b1) \
    asm volatile("mma.sync.aligned.m16n8k16.row.col.f32.f16.f16.f32 " \
                 "{%0,%1,%2,%3},{%4,%5,%6,%7},{%8,%9},{%0,%1,%2,%3};" \
                 : "+f"((d)[0]), "+f"((d)[1]), "+f"((d)[2]), "+f"((d)[3]) \
                 : "r"((a)[0]), "r"((a)[1]), "r"((a)[2]), "r"((a)[3]), "r"(b0), "r"(b1))

// ---------------------------------------------------------------------------
// GroupNorm phase 1: per-(b,g) mean / rstd
// ---------------------------------------------------------------------------
__global__ __launch_bounds__(256) void gn_stats_kernel(
    const float* __restrict__ x, float* __restrict__ stats)
{
    const int GSZ = (CH / NGRP) * NPIX;
    const int bg  = blockIdx.x;
    const float4* xv = (const float4*)(x + (size_t)bg * GSZ);
    const int tid = threadIdx.x;

    float s = 0.f, ss = 0.f;
    for (int i = tid; i < GSZ / 4; i += 256) {
        float4 v = xv[i];
        s  += v.x + v.y + v.z + v.w;
        ss += v.x * v.x + v.y * v.y + v.z * v.z + v.w * v.w;
    }
    __shared__ float rs[256], rss[256];
    rs[tid] = s; rss[tid] = ss;
    __syncthreads();
    for (int o = 128; o > 0; o >>= 1) {
        if (tid < o) { rs[tid] += rs[tid + o]; rss[tid] += rss[tid + o]; }
        __syncthreads();
    }
    if (tid == 0) {
        float mu  = rs[0] / GSZ;
        float var = rss[0] / GSZ - mu * mu;
        stats[bg * 2]     = mu;
        stats[bg * 2 + 1] = rsqrtf(var + 1e-5f);
    }
}

// ---------------------------------------------------------------------------
// GroupNorm phase 2: normalize + transpose -> ht[b][p][c] (fp16)
// 32 channels x 64 pixels per block; load phase MLP=8, smem transpose,
// half2 stores along c.
// ---------------------------------------------------------------------------
__global__ __launch_bounds__(256) void gn_apply_kernel(
    const float* __restrict__ x, const float* __restrict__ gamma,
    const float* __restrict__ beta, const float* __restrict__ stats,
    __half* __restrict__ ht)
{
    __shared__ float s[32][65];
    const int p0 = blockIdx.x * 64, c0 = blockIdx.y * 32, b = blockIdx.z;
    const int tid = threadIdx.x;

    // load: thread -> pixel p0 + (tid&63), channel c0 + (tid>>6) + 4*q
    const int pj = tid & 63;
    const int cb = tid >> 6;                       // 0..3
    #pragma unroll
    for (int q = 0; q < 8; q++) {
        const int ci = cb + q * 4;
        const int c = c0 + ci;
        const int g = c >> 4;
        const float mu = stats[(b * NGRP + g) * 2];
        const float rinv = stats[(b * NGRP + g) * 2 + 1];
        float xv = x[((size_t)b * CH + c) * NPIX + p0 + pj];
        s[ci][pj] = (xv - mu) * rinv * gamma[c] + beta[c];
    }
    __syncthreads();
    // store: thread -> c pair (tid&15)*2, pixel p0 + (tid>>4) + 16*q
    const int cj = (tid & 15) * 2;
    const int pb = tid >> 4;                       // 0..15
    #pragma unroll
    for (int q = 0; q < 4; q++) {
        const int pi = pb + q * 16;
        __half2 h(__float2half(s[cj][pi]), __float2half(s[cj + 1][pi]));
        *(__half2*)(ht + (size_t)b * NPIX * CH + (size_t)(p0 + pi) * CH + c0 + cj) = h;
    }
}

// ---------------------------------------------------------------------------
// Row softmax -> fp16 P. 4 rows per 256-thread block: each 64-thread quarter
// (= 2 warps) owns one row, 4 x float4 per thread (MLP=4). Reductions:
// warp shfl -> per-warp smem slot -> combine 2 slots. Two block barriers.
// ---------------------------------------------------------------------------
__global__ __launch_bounds__(256) void softmax_kernel(
    const float* __restrict__ attn, __half* __restrict__ ph)
{
    const int tid  = threadIdx.x;
    const int qtr  = tid >> 6;                 // 0..3
    const int t    = tid & 63;
    const int lane = tid & 31, wrp = tid >> 5; // 0..7
    const size_t row = (size_t)blockIdx.x * 4 + qtr;

    const float4* p = (const float4*)(attn + row * NPIX);
    float4 v[4];
    #pragma unroll
    for (int j = 0; j < 4; j++) v[j] = p[t + j * 64];

    __shared__ float redm[8], reds[8];

    float m = -1e30f;
    #pragma unroll
    for (int j = 0; j < 4; j++)
        m = fmaxf(m, fmaxf(fmaxf(v[j].x, v[j].y), fmaxf(v[j].z, v[j].w)));
    #pragma unroll
    for (int o = 16; o > 0; o >>= 1) m = fmaxf(m, __shfl_xor_sync(~0u, m, o));
    if (lane == 0) redm[wrp] = m;
    __syncthreads();
    const float rmax = fmaxf(redm[qtr * 2], redm[qtr * 2 + 1]);

    float s = 0.f;
    #pragma unroll
    for (int j = 0; j < 4; j++) {
        v[j].x = __expf(v[j].x - rmax); v[j].y = __expf(v[j].y - rmax);
        v[j].z = __expf(v[j].z - rmax); v[j].w = __expf(v[j].w - rmax);
        s += v[j].x + v[j].y + v[j].z + v[j].w;
    }
    #pragma unroll
    for (int o = 16; o > 0; o >>= 1) s += __shfl_xor_sync(~0u, s, o);
    if (lane == 0) reds[wrp] = s;
    __syncthreads();
    const float tot = reds[qtr * 2] + reds[qtr * 2 + 1];

    const float rinv = 1.f / tot;
    uint2* po = (uint2*)(ph + row * NPIX);
    #pragma unroll
    for (int j = 0; j < 4; j++) {
        __half2 h0(__float2half(v[j].x * rinv), __float2half(v[j].y * rinv));
        __half2 h1(__float2half(v[j].z * rinv), __float2half(v[j].w * rinv));
        uint2 u; u.x = *(uint32_t*)&h0; u.y = *(uint32_t*)&h1;
        po[t + j * 64] = u;
    }
}

// ---------------------------------------------------------------------------
// fp32 -> fp16, both weight tensors in one grid-stride launch
// ---------------------------------------------------------------------------
__global__ __launch_bounds__(256) void pack_kernel(
    const float* __restrict__ w0, __half* __restrict__ o0, int n0,
    const float* __restrict__ w1, __half* __restrict__ o1, int n1)
{
    const int stride = gridDim.x * 256;
    for (int i = (blockIdx.x * 256 + threadIdx.x) * 2; i < n0; i += stride * 2)
        *(__half2*)(o0 + i) = __half2(__float2half(w0[i]), __float2half(w0[i + 1]));
    for (int i = (blockIdx.x * 256 + threadIdx.x) * 2; i < n1; i += stride * 2)
        *(__half2*)(o1 + i) = __half2(__float2half(w1[i]), __float2half(w1[i + 1]));
}

// ---------------------------------------------------------------------------
// fp16 HMMA GEMM: D[m][n] = sum_k A[m][k]*B[n][k] (both k-major, fp16).
// CTA 128x128, BK=32, 8 warps (2M x 4N), warp tile 64x32, 4-stage cp.async,
// one __syncthreads per k-iter, 2 CTAs/SM.
// smem rows 64B, 16B units XOR-swizzled by (row>>1)&3.
// Direct-register epilogue for row-major outputs (scores/PV/proj/V);
// smem-staged transpose only for Q/K.
// EPI 0: QKV  1: scores  2: PV  3: proj(+bias+residual)
// ---------------------------------------------------------------------------
template<int EPI>
__global__ __launch_bounds__(256, 2) void tc_gemm(
    const __half* __restrict__ Ag, const __half* __restrict__ Bg,
    long long sAb, long long sBb, int ldA, int ldB, int K,
    const float* __restrict__ bias, float scale,
    float* __restrict__ outf,
    __half* __restrict__ o0, __half* __restrict__ o1, __half* __restrict__ o2,
    const float* __restrict__ resid)
{
    extern __shared__ char smem[];
    const uint32_t sb = smem_u32(smem);
    const int tid = threadIdx.x;
    const int lane = tid & 31, wid = tid >> 5;
    const int bz = blockIdx.z;
    const int m0 = blockIdx.y * TM;
    const int n0 = blockIdx.x * TN;

    const __half* Ap = Ag + (size_t)bz * sAb + (size_t)m0 * ldA;
    const __half* Bp = Bg + (size_t)bz * sBb + (size_t)n0 * ldB;

    // loaders: row = tid>>1 (0..127), 2 of 4 16B units each
    const int lrow = tid >> 1;
    const int usel = tid & 1;

    auto load_tile = [&](int buf, int k0) {
        const uint32_t sa  = sb + buf * STAGE_BYTES;
        const uint32_t sbB = sa + A_STAGE;
        const int rsw = (lrow >> 1) & 3;
        #pragma unroll
        for (int j = 0; j < 2; j++) {
            const int u = usel * 2 + j;
            const uint32_t sw = (uint32_t)((u ^ rsw) << 4);
            CP16(sa  + lrow * 64 + sw, Ap + (size_t)lrow * ldA + k0 + u * 8);
            CP16(sbB + lrow * 64 + sw, Bp + (size_t)lrow * ldB + k0 + u * 8);
        }
    };

    // warp layout: 2 (M) x 4 (N), warp tile 64x32
    const int wm = wid >> 2, wn = wid & 3;
    const int m_base = wm * 64, n_base = wn * 32;

    // ldmatrix lane mapping
    const int amat = lane >> 3;
    const int arow = (amat & 1) * 8 + (lane & 7);
    const int auadd = amat >> 1;
    const int bmat = lane >> 3;
    const int bnrow = (bmat >> 1) * 8 + (lane & 7);
    const int buadd = bmat & 1;

    float acc[4][4][4] = {};

    const int nk = K / TK;
    load_tile(0, 0);
    CP_COMMIT();
    load_tile(1, TK);
    CP_COMMIT();
    load_tile(2, 2 * TK);
    CP_COMMIT();

    for (int i = 0; i < nk; i++) {
        if (i == nk - 1) { CP_WAIT0(); } else { CP_WAIT2(); }
        __syncthreads();
        if (i + 3 < nk) {
            load_tile((i + 3) % NSTAGE, (i + 3) * TK);
            CP_COMMIT();
        }
        const uint32_t sa  = sb + (i % NSTAGE) * STAGE_BYTES;
        const uint32_t sbB = sa + A_STAGE;

        #pragma unroll
        for (int kk = 0; kk < 2; kk++) {
            uint32_t bh[8];
            #pragma unroll
            for (int np = 0; np < 2; np++) {
                const int n = n_base + np * 16 + bnrow;
                const int uh = kk * 2 + buadd;
                LDSM4(bh[np * 4 + 0], bh[np * 4 + 1], bh[np * 4 + 2], bh[np * 4 + 3],
                      sbB + n * 64 + ((uh ^ ((n >> 1) & 3)) << 4));
            }
            uint32_t ah[4][4];
            #pragma unroll
            for (int mt = 0; mt < 4; mt++) {
                const int row = m_base + mt * 16 + arow;
                const int uh = kk * 2 + auadd;
                LDSM4(ah[mt][0], ah[mt][1], ah[mt][2], ah[mt][3],
                      sa + row * 64 + ((uh ^ ((row >> 1) & 3)) << 4));
            }
            #pragma unroll
            for (int mt = 0; mt < 4; mt++)
                #pragma unroll
                for (int nt = 0; nt < 4; nt++) {
                    const int r = (nt >> 1) * 4 + (nt & 1) * 2;
                    MMA_F16(acc[mt][nt], ah[mt], bh[r], bh[r + 1]);
                }
        }
    }

    // ---- epilogues ----
    const int rowL = lane >> 2;            // 0..7
    const int colL = (lane & 3) * 2;       // 0..6

    if (EPI == 0 && m0 < 2 * CH) {
        // Q or K tile: needs transpose -> smem staging
        __syncthreads();
        float* s = (float*)smem;
        #pragma unroll
        for (int mt = 0; mt < 4; mt++)
            #pragma unroll
            for (int nt = 0; nt < 4; nt++)
                #pragma unroll
                for (int r = 0; r < 4; r++) {
                    const int row = m_base + mt * 16 + rowL + (r >= 2 ? 8 : 0);
                    const int col = n_base + nt * 8 + colL + (r & 1);
                    s[row * SPITCH + col] = acc[mt][nt][r];
                }
        __syncthreads();
        __half* d = (m0 < CH ? o0 : o1) + (size_t)bz * NPIX * CH;
        const int coff = m0 & (CH - 1);
        for (int it = 0; it < 32; it++) {
            const int idx = it * 512 + tid * 2;
            const int n = idx >> 7, m = idx & 127;
            float v0 = s[m * SPITCH + n] + bias[m0 + m];
            float v1 = s[(m + 1) * SPITCH + n] + bias[m0 + m + 1];
            const size_t o = (size_t)(n0 + n) * CH + coff + m;
            *(__half2*)(d + o) = __half2(__float2half(v0), __float2half(v1));
        }
    } else {
        // direct-register writers: acc pairs are adjacent output columns
        #pragma unroll
        for (int mt = 0; mt < 4; mt++) {
            #pragma unroll
            for (int nt = 0; nt < 4; nt++) {
                const int col = n_base + nt * 8 + colL;
                #pragma unroll
                for (int h = 0; h < 2; h++) {       // h=0: rows+0, h=1: rows+8
                    const int row = m_base + mt * 16 + rowL + h * 8;
                    const float a0 = acc[mt][nt][h * 2];
                    const float a1 = acc[mt][nt][h * 2 + 1];
                    if (EPI == 0) {          // V tile -> v[b][c][p] fp16 (+bias)
                        const int c = m0 - 2 * CH + row;
                        const float bv = bias[m0 + row];
                        const size_t o = ((size_t)bz * CH + c) * NPIX + n0 + col;
                        *(__half2*)(o2 + o) =
                            __half2(__float2half(a0 + bv), __float2half(a1 + bv));
                    } else if (EPI == 1) {   // scores fp32 * scale
                        const size_t o = ((size_t)bz * NPIX + m0 + row) * NPIX + n0 + col;
                        *(float2*)(outf + o) = make_float2(a0 * scale, a1 * scale);
                    } else if (EPI == 2) {   // Ot fp16 [p][c]
                        const size_t o = ((size_t)bz * NPIX + m0 + row) * CH + n0 + col;
                        *(__half2*)(o0 + o) =
                            __half2(__float2half(a0), __float2half(a1));
                    } else {                 // proj + bias + residual fp32
                        const float bv = bias[m0 + row];
                        const size_t o = ((size_t)bz * CH + m0 + row) * NPIX + n0 + col;
                        float2 rv = *(const float2*)(resid + o);
                        *(float2*)(outf + o) =
                            make_float2(a0 + bv + rv.x, a1 + bv + rv.y);
                    }
                }
            }
        }
    }
}

// ---------------------------------------------------------------------------
extern "C" void kernel_launch(void* const* d_in, const int* in_sizes, int n_in,
                              void* d_out, int out_size)
{
    const float* x      = (const float*)d_in[0];
    const float* gamma  = (const float*)d_in[1];
    const float* beta   = (const float*)d_in[2];
    const float* w_qkv  = (const float*)d_in[3];
    const float* b_qkv  = (const float*)d_in[4];
    const float* w_proj = (const float*)d_in[5];
    const float* b_proj = (const float*)d_in[6];
    float* out = (float*)d_out;

    __half *ht, *qq, *kk, *vv, *pp, *ot, *wq, *wp;
    float *attn, *stats;
    cudaGetSymbolAddress((void**)&ht, g_ht);
    cudaGetSymbolAddress((void**)&qq, g_q );
    cudaGetSymbolAddress((void**)&kk, g_k );
    cudaGetSymbolAddress((void**)&vv, g_v );
    cudaGetSymbolAddress((void**)&pp, g_p );
    cudaGetSymbolAddress((void**)&ot, g_ot);
    cudaGetSymbolAddress((void**)&wq, g_wq);
    cudaGetSymbolAddress((void**)&wp, g_wp);
    cudaGetSymbolAddress((void**)&attn, g_attn);
    cudaGetSymbolAddress((void**)&stats, g_stats);

    cudaFuncSetAttribute(tc_gemm<0>, cudaFuncAttributeMaxDynamicSharedMemorySize, SMEM_BYTES);
    cudaFuncSetAttribute(tc_gemm<1>, cudaFuncAttributeMaxDynamicSharedMemorySize, SMEM_BYTES);
    cudaFuncSetAttribute(tc_gemm<2>, cudaFuncAttributeMaxDynamicSharedMemorySize, SMEM_BYTES);
    cudaFuncSetAttribute(tc_gemm<3>, cudaFuncAttributeMaxDynamicSharedMemorySize, SMEM_BYTES);

    const long long sH = (long long)NPIX * CH;
    const long long sP = (long long)NPIX * NPIX;

    pack_kernel<<<1024, 256>>>(w_qkv, wq, 3 * CH * CH, w_proj, wp, CH * CH);
    gn_stats_kernel<<<NB * NGRP, 256>>>(x, stats);
    gn_apply_kernel<<<dim3(NPIX / 64, CH / 32, NB), 256>>>(x, gamma, beta, stats, ht);

    // QKV: A = w_qkv, B = ht -> q [p][c], k [p][c], v [c][p]
    tc_gemm<0><<<dim3(NPIX / TN, 1536 / TM, NB), 256, SMEM_BYTES>>>(
        wq, ht, 0, sH, CH, CH, CH,
        b_qkv, 1.f, nullptr, qq, kk, vv, nullptr);

    // scores: A = q, B = k -> attn fp32
    tc_gemm<1><<<dim3(NPIX / TN, NPIX / TM, NB), 256, SMEM_BYTES>>>(
        qq, kk, sH, sH, CH, CH, CH,
        nullptr, 1.0f / sqrtf((float)CH), attn,
        nullptr, nullptr, nullptr, nullptr);

    softmax_kernel<<<NB * NPIX / 4, 256>>>(attn, pp);

    // PV: A = p, B = v -> ot [p][c]
    tc_gemm<2><<<dim3(CH / TN, NPIX / TM, NB), 256, SMEM_BYTES>>>(
        pp, vv, sP, sH, NPIX, NPIX, NPIX,
        nullptr, 1.f, nullptr, ot, nullptr, nullptr, nullptr);

    // proj: A = w_proj, B = ot + bias + residual -> out fp32
    tc_gemm<3><<<dim3(NPIX / TN, CH / TM, NB), 256, SMEM_BYTES>>>(
        wp, ot, 0, sH, CH, CH, CH,
        b_proj, 1.f, out, nullptr, nullptr, nullptr, x);
}